// round 8
// baseline (speedup 1.0000x reference)
#include <cuda_runtime.h>
#include <cuda_fp16.h>
#include <cstdint>

// Problem constants
#define Bb   8
#define Lseq 8192
#define Hd   768
#define Mtot (Bb * Lseq)        // 65536
#define LAMK 0.1f

// GEMM tiling: CTA 128M x 128 a-cols (+128 g-cols), warp-specialized pipeline
#define KT    24                // K chunks of 32
#define RSB   80                // smem row stride bytes -> conflict-free ldmatrix
#define ATILE 10240             // 128 rows * 80B
#define BTILE 20480             // 256 rows * 80B (a rows then g rows)
#define STG   (ATILE + BTILE)   // 30720
#define NST   6                 // pipeline stages
#define HDR   128               // mbarrier region
#define GSM   (HDR + NST * STG) // 184448 bytes dynamic smem

// ---------------- scratch ----------------------------------------------------
__device__ __half g_vh[(size_t)Mtot * Hd];      // silu(x*D + conv) in fp16
__device__ __half g_wh[2 * Hd * Hd];            // W in fp16 (1536 x 768)
__device__ int    g_tap_idx[Hd * Lseq];
__device__ float  g_tap_val[Hd * Lseq];
__device__ int    g_tap_cnt[Hd];

// ---------------- helpers ----------------------------------------------------
__device__ __forceinline__ float sigmoidf_(float z) {
    return 1.0f / (1.0f + __expf(-z));
}

__device__ __forceinline__ uint32_t s2u(const void* p) {
    uint32_t a;
    asm("{ .reg .u64 t; cvta.to.shared.u64 t, %1; cvt.u32.u64 %0, t; }"
        : "=r"(a) : "l"(p));
    return a;
}

__device__ __forceinline__ void cp16(uint32_t dst, const void* src) {
    asm volatile("cp.async.cg.shared.global [%0], [%1], 16;\n"
                 :: "r"(dst), "l"(src));
}

__device__ __forceinline__ void ldsm4(uint32_t* r, uint32_t addr) {
    asm volatile("ldmatrix.sync.aligned.m8n8.x4.shared.b16 {%0,%1,%2,%3}, [%4];"
                 : "=r"(r[0]), "=r"(r[1]), "=r"(r[2]), "=r"(r[3]) : "r"(addr));
}

__device__ __forceinline__ void mma16816(float* d, const uint32_t* a,
                                         uint32_t b0, uint32_t b1) {
    asm volatile(
        "mma.sync.aligned.m16n8k16.row.col.f32.f16.f16.f32 "
        "{%0,%1,%2,%3}, {%4,%5,%6,%7}, {%8,%9}, {%0,%1,%2,%3};\n"
        : "+f"(d[0]), "+f"(d[1]), "+f"(d[2]), "+f"(d[3])
        : "r"(a[0]), "r"(a[1]), "r"(a[2]), "r"(a[3]), "r"(b0), "r"(b1));
}

// consumer wait: acquire ordering (generic shared loads follow)
__device__ __forceinline__ void mbar_wait_acq(uint32_t mbar, uint32_t parity) {
    asm volatile(
        "{\n\t"
        ".reg .pred P;\n\t"
        "WL%=:\n\t"
        "mbarrier.try_wait.parity.acquire.cta.shared::cta.b64 P, [%0], %1;\n\t"
        "@P bra WD%=;\n\t"
        "bra WL%=;\n\t"
        "WD%=:\n\t"
        "}"
        :: "r"(mbar), "r"(parity) : "memory");
}

// producer wait: post-wait accesses are cp.async writes (async proxy)
__device__ __forceinline__ void mbar_wait(uint32_t mbar, uint32_t parity) {
    asm volatile(
        "{\n\t"
        ".reg .pred P;\n\t"
        "WL%=:\n\t"
        "mbarrier.try_wait.parity.shared::cta.b64 P, [%0], %1;\n\t"
        "@P bra WD%=;\n\t"
        "bra WL%=;\n\t"
        "WD%=:\n\t"
        "}"
        :: "r"(mbar), "r"(parity) : "memory");
}

__device__ __forceinline__ void mbar_arrive(uint32_t mbar) {
    asm volatile("mbarrier.arrive.release.cta.shared::cta.b64 _, [%0];"
                 :: "r"(mbar) : "memory");
}

// ---------------- kernel 0: W fp32 -> fp16 -----------------------------------
__global__ void wconv_kernel(const float* __restrict__ W) {
    int i = blockIdx.x * 256 + threadIdx.x;
    g_wh[i] = __float2half_rn(W[i]);
}

// ---------------- kernel 1: soft-threshold + ordered tap compaction ----------
__global__ void build_taps_kernel(const float* __restrict__ kern) {
    int h = blockIdx.x * 8 + (threadIdx.x >> 5);
    int lane = threadIdx.x & 31;
    const float* kr = kern + (size_t)h * Lseq;
    int* ti = g_tap_idx + (size_t)h * Lseq;
    float* tv = g_tap_val + (size_t)h * Lseq;
    int cnt = 0;
    for (int base = 0; base < Lseq; base += 32) {
        float kv = kr[base + lane];
        float mag = fabsf(kv) - LAMK;
        bool p = mag > 0.0f;
        unsigned msk = __ballot_sync(0xffffffffu, p);
        if (p) {
            int pos = cnt + __popc(msk & ((1u << lane) - 1u));
            ti[pos] = base + lane;
            tv[pos] = copysignf(mag, kv);
        }
        cnt += __popc(msk);
    }
    if (lane == 0) g_tap_cnt[h] = cnt;
}

// ---------------- kernel 2: v = silu(x*D + sparse_causal_conv) -> fp16 -------
__global__ void prep_v_kernel(const float* __restrict__ x, const float* __restrict__ D) {
    const int H4 = Hd / 4;
    int i = blockIdx.x * blockDim.x + threadIdx.x;
    int m = i / H4;
    int h4 = (i - m * H4) * 4;

    float4 xv = *reinterpret_cast<const float4*>(x + (size_t)m * Hd + h4);
    float4 dv = *reinterpret_cast<const float4*>(D + h4);
    float s[4] = { xv.x * dv.x, xv.y * dv.y, xv.z * dv.z, xv.w * dv.w };

#pragma unroll
    for (int c = 0; c < 4; ++c) {
        int h = h4 + c;
        int cnt = g_tap_cnt[h];
        if (cnt > 0) {                         // cold path (taps survive threshold)
            int l = m & (Lseq - 1);
            int b = m >> 13;
            const int* ti = g_tap_idx + (size_t)h * Lseq;
            const float* tv = g_tap_val + (size_t)h * Lseq;
            float acc = 0.0f;
            for (int t = 0; t < cnt; ++t) {
                int j = ti[t];
                if (j <= l)
                    acc += tv[t] * x[((size_t)b * Lseq + (l - j)) * Hd + h];
            }
            s[c] += acc;
        }
    }

    __half2 h01 = __floats2half2_rn(s[0] * sigmoidf_(s[0]), s[1] * sigmoidf_(s[1]));
    __half2 h23 = __floats2half2_rn(s[2] * sigmoidf_(s[2]), s[3] * sigmoidf_(s[3]));
    uint2 pk;
    pk.x = *reinterpret_cast<uint32_t*>(&h01);
    pk.y = *reinterpret_cast<uint32_t*>(&h23);
    *reinterpret_cast<uint2*>(g_vh + (size_t)m * Hd + h4) = pk;
}

// ---------------- kernel 3: warp-specialized fp16 GEMM + GLU + residual ------
// Warps 0..7: compute (2M x 4N grid, warp tile 64M x 32a+32g)
// Warp 8: producer (cp.async all A/B tiles through a 6-stage mbarrier ring)
__global__ void __launch_bounds__(288, 1)
gemm_fp16_kernel(const float* __restrict__ bias, const float* __restrict__ x,
                 float* __restrict__ out) {
    extern __shared__ char dsm[];
    uint32_t sb = s2u(dsm);
    const int tid  = threadIdx.x;
    const int lane = tid & 31;
    const int warp = tid >> 5;
    const int m0 = blockIdx.y * 128;
    const int n0 = blockIdx.x * 128;

    // mbarriers: full[s] at sb + 8s (count 32), empty[s] at sb + 48 + 8s (count 8)
    if (tid == 0) {
#pragma unroll
        for (int s = 0; s < NST; ++s) {
            asm volatile("mbarrier.init.shared.b64 [%0], %1;"
                         :: "r"(sb + 8 * s), "r"(32) : "memory");
            asm volatile("mbarrier.init.shared.b64 [%0], %1;"
                         :: "r"(sb + 48 + 8 * s), "r"(8) : "memory");
        }
    }
    __syncthreads();

    if (warp == 8) {
        // ---------------- producer ----------------
        const int lq = lane & 3;        // 16B unit within row
        const int lr = lane >> 2;       // base row 0..7
        const __half* asrc  = g_vh + (size_t)(m0 + lr) * Hd + lq * 8;
        const __half* bsrc1 = g_wh + (size_t)(n0 + lr) * Hd + lq * 8;        // a rows
        const __half* bsrc2 = g_wh + (size_t)(Hd + n0 + lr) * Hd + lq * 8;   // g rows: W row 768+n0+(lr+8j)
        const uint32_t adst = (uint32_t)(lr * RSB + lq * 16);

        for (int t = 0; t < KT; ++t) {
            int s = t % NST;
            int u = t / NST;
            if (t >= NST) mbar_wait(sb + 48 + 8 * s, (uint32_t)((u - 1) & 1));
            uint32_t st = sb + HDR + s * STG;
            int kw = t * 32;
#pragma unroll
            for (int j = 0; j < 16; ++j)            // A: rows lr+8j
                cp16(st + adst + j * (8 * RSB),
                     asrc + (size_t)(8 * j) * Hd + kw);
#pragma unroll
            for (int j = 0; j < 16; ++j)            // B a-half: rows lr+8j
                cp16(st + ATILE + adst + j * (8 * RSB),
                     bsrc1 + (size_t)(8 * j) * Hd + kw);
#pragma unroll
            for (int j = 0; j < 16; ++j)            // B g-half: dst rows 128+lr+8j
                cp16(st + ATILE + 128 * RSB + adst + j * (8 * RSB),
                     bsrc2 + (size_t)(8 * j) * Hd + kw);
            asm volatile("cp.async.mbarrier.arrive.noinc.shared::cta.b64 [%0];"
                         :: "r"(sb + 8 * s) : "memory");
        }
        return;
    }

    // ---------------- consumers ----------------
    const int wm = warp >> 2;            // 0..1 -> 64 M-rows
    const int wn = warp & 3;             // 0..3 -> 32 a-cols (+32 g-cols)

    const int lro = (lane & 7) + ((lane >> 3) & 1) * 8;
    const int lu  = lane >> 4;
    uint32_t aoff[4], boffA[2], boffG[2];
#pragma unroll
    for (int mi = 0; mi < 4; ++mi)
        aoff[mi] = (uint32_t)((wm * 64 + mi * 16 + lro) * RSB + lu * 16);
#pragma unroll
    for (int hh = 0; hh < 2; ++hh) {
        boffA[hh] = (uint32_t)(ATILE + (wn * 32 + hh * 16 + lro) * RSB + lu * 16);
        boffG[hh] = (uint32_t)(ATILE + (128 + wn * 32 + hh * 16 + lro) * RSB + lu * 16);
    }

    float accA[4][4][4], accG[4][4][4];
#pragma unroll
    for (int mi = 0; mi < 4; ++mi)
#pragma unroll
        for (int nj = 0; nj < 4; ++nj)
#pragma unroll
            for (int r = 0; r < 4; ++r) { accA[mi][nj][r] = 0.f; accG[mi][nj][r] = 0.f; }

    for (int t = 0; t < KT; ++t) {
        int s = t % NST;
        int u = t / NST;
        mbar_wait_acq(sb + 8 * s, (uint32_t)(u & 1));
        uint32_t bbase = sb + HDR + s * STG;
#pragma unroll
        for (int ks = 0; ks < 2; ++ks) {
            uint32_t kadd = (uint32_t)(ks * 32);   // 16 halves = 32B
            uint32_t afr[4][4];
#pragma unroll
            for (int mi = 0; mi < 4; ++mi)
                ldsm4(afr[mi], bbase + aoff[mi] + kadd);
            uint32_t ba[2][4], bg[2][4];
#pragma unroll
            for (int hh = 0; hh < 2; ++hh) {
                ldsm4(ba[hh], bbase + boffA[hh] + kadd);
                ldsm4(bg[hh], bbase + boffG[hh] + kadd);
            }
#pragma unroll
            for (int mi = 0; mi < 4; ++mi)
#pragma unroll
                for (int hh = 0; hh < 2; ++hh) {
                    mma16816(accA[mi][2 * hh + 0], afr[mi], ba[hh][0], ba[hh][2]);
                    mma16816(accA[mi][2 * hh + 1], afr[mi], ba[hh][1], ba[hh][3]);
                    mma16816(accG[mi][2 * hh + 0], afr[mi], bg[hh][0], bg[hh][2]);
                    mma16816(accG[mi][2 * hh + 1], afr[mi], bg[hh][1], bg[hh][3]);
                }
        }
        if (lane == 0) mbar_arrive(sb + 48 + 8 * s);
    }

    // epilogue: bias + GLU + residual
    const int r  = lane >> 2;
    const int c2 = (lane & 3) * 2;
#pragma unroll
    for (int nj = 0; nj < 4; ++nj) {
        int col = n0 + wn * 32 + ((nj >> 1) * 16) + (nj & 1) * 8 + c2;
        float ba0 = __ldg(bias + col),      ba1 = __ldg(bias + col + 1);
        float bg0 = __ldg(bias + Hd + col), bg1 = __ldg(bias + Hd + col + 1);
#pragma unroll
        for (int mi = 0; mi < 4; ++mi) {
            int mrow = m0 + wm * 64 + mi * 16 + r;
            {
                float a0 = accA[mi][nj][0] + ba0, a1 = accA[mi][nj][1] + ba1;
                float g0 = accG[mi][nj][0] + bg0, g1 = accG[mi][nj][1] + bg1;
                float2 xv = __ldg(reinterpret_cast<const float2*>(x + (size_t)mrow * Hd + col));
                float2 o;
                o.x = a0 * sigmoidf_(g0) + xv.x;
                o.y = a1 * sigmoidf_(g1) + xv.y;
                *reinterpret_cast<float2*>(out + (size_t)mrow * Hd + col) = o;
            }
            {
                int mr2 = mrow + 8;
                float a0 = accA[mi][nj][2] + ba0, a1 = accA[mi][nj][3] + ba1;
                float g0 = accG[mi][nj][2] + bg0, g1 = accG[mi][nj][3] + bg1;
                float2 xv = __ldg(reinterpret_cast<const float2*>(x + (size_t)mr2 * Hd + col));
                float2 o;
                o.x = a0 * sigmoidf_(g0) + xv.x;
                o.y = a1 * sigmoidf_(g1) + xv.y;
                *reinterpret_cast<float2*>(out + (size_t)mr2 * Hd + col) = o;
            }
        }
    }
}

// ---------------- launch ------------------------------------------------------
extern "C" void kernel_launch(void* const* d_in, const int* in_sizes, int n_in,
                              void* d_out, int out_size) {
    const float* x    = (const float*)d_in[0];   // (8, 8192, 768)
    const float* kern = (const float*)d_in[1];   // (1, 768, 8192)
    const float* D    = (const float*)d_in[2];   // (1, 768)
    const float* W    = (const float*)d_in[3];   // (1536, 768)
    const float* bias = (const float*)d_in[4];   // (1536,)
    float* out = (float*)d_out;                  // (8, 8192, 768)

    cudaFuncSetAttribute(gemm_fp16_kernel,
                         cudaFuncAttributeMaxDynamicSharedMemorySize, GSM);

    wconv_kernel<<<(2 * Hd * Hd) / 256, 256>>>(W);
    build_taps_kernel<<<Hd / 8, 256>>>(kern);

    int tot4 = Mtot * (Hd / 4);
    prep_v_kernel<<<tot4 / 256, 256>>>(x, D);

    dim3 grid(Hd / 128, Mtot / 128);             // (6, 512)
    gemm_fp16_kernel<<<grid, 288, GSM>>>(bias, x, out);
}

// round 9
// speedup vs baseline: 1.3427x; 1.3427x over previous
#include <cuda_runtime.h>
#include <cuda_fp16.h>
#include <cstdint>

// Problem constants
#define Bb   8
#define Lseq 8192
#define Hd   768
#define Mtot (Bb * Lseq)        // 65536
#define LAMK 0.1f

// GEMM tiling (fp16 mma.sync path, fp16 accumulate)
#define KT    24                // K chunks of 32
#define RSB   80                // smem row stride bytes (40 halves) -> conflict-free ldmatrix
#define ATILE 10240             // 128 rows * 80B
#define STG   20480             // A tile + B tile per stage
#define NSTG  4
#define GSM   (NSTG * STG)      // 81920 bytes dynamic smem

// ---------------- scratch ----------------------------------------------------
__device__ __half g_vh[(size_t)Mtot * Hd];      // silu(x*D + conv) in fp16
__device__ __half g_wh[2 * Hd * Hd];            // W in fp16 (1536 x 768)
__device__ int    g_tap_idx[Hd * Lseq];
__device__ float  g_tap_val[Hd * Lseq];
__device__ int    g_tap_cnt[Hd];

// ---------------- helpers ----------------------------------------------------
__device__ __forceinline__ float sigmoidf_(float z) {
    return 1.0f / (1.0f + __expf(-z));
}

__device__ __forceinline__ uint32_t s2u(const void* p) {
    uint32_t a;
    asm("{ .reg .u64 t; cvta.to.shared.u64 t, %1; cvt.u32.u64 %0, t; }"
        : "=r"(a) : "l"(p));
    return a;
}

__device__ __forceinline__ void cp16(uint32_t dst, const void* src) {
    asm volatile("cp.async.cg.shared.global [%0], [%1], 16;\n"
                 :: "r"(dst), "l"(src));
}

__device__ __forceinline__ void ldsm4(uint32_t* r, uint32_t addr) {
    asm volatile("ldmatrix.sync.aligned.m8n8.x4.shared.b16 {%0,%1,%2,%3}, [%4];"
                 : "=r"(r[0]), "=r"(r[1]), "=r"(r[2]), "=r"(r[3]) : "r"(addr));
}

// fp16-accumulate mma: D,C are 2 regs of f16x2
__device__ __forceinline__ void mma16816h(uint32_t* d, const uint32_t* a,
                                          uint32_t b0, uint32_t b1) {
    asm volatile(
        "mma.sync.aligned.m16n8k16.row.col.f16.f16.f16.f16 "
        "{%0,%1}, {%2,%3,%4,%5}, {%6,%7}, {%0,%1};\n"
        : "+r"(d[0]), "+r"(d[1])
        : "r"(a[0]), "r"(a[1]), "r"(a[2]), "r"(a[3]), "r"(b0), "r"(b1));
}

// ---------------- kernel 0: W fp32 -> fp16 -----------------------------------
__global__ void wconv_kernel(const float* __restrict__ W) {
    int i = blockIdx.x * 256 + threadIdx.x;
    g_wh[i] = __float2half_rn(W[i]);
}

// ---------------- kernel 1: soft-threshold + ordered tap compaction ----------
__global__ void build_taps_kernel(const float* __restrict__ kern) {
    int h = blockIdx.x * 8 + (threadIdx.x >> 5);
    int lane = threadIdx.x & 31;
    const float* kr = kern + (size_t)h * Lseq;
    int* ti = g_tap_idx + (size_t)h * Lseq;
    float* tv = g_tap_val + (size_t)h * Lseq;
    int cnt = 0;
    for (int base = 0; base < Lseq; base += 32) {
        float kv = kr[base + lane];
        float mag = fabsf(kv) - LAMK;
        bool p = mag > 0.0f;
        unsigned msk = __ballot_sync(0xffffffffu, p);
        if (p) {
            int pos = cnt + __popc(msk & ((1u << lane) - 1u));
            ti[pos] = base + lane;
            tv[pos] = copysignf(mag, kv);
        }
        cnt += __popc(msk);
    }
    if (lane == 0) g_tap_cnt[h] = cnt;
}

// ---------------- kernel 2: v = silu(x*D + sparse_causal_conv) -> fp16 -------
__global__ void prep_v_kernel(const float* __restrict__ x, const float* __restrict__ D) {
    const int H4 = Hd / 4;
    int i = blockIdx.x * blockDim.x + threadIdx.x;
    int m = i / H4;
    int h4 = (i - m * H4) * 4;

    float4 xv = *reinterpret_cast<const float4*>(x + (size_t)m * Hd + h4);
    float4 dv = *reinterpret_cast<const float4*>(D + h4);
    float s[4] = { xv.x * dv.x, xv.y * dv.y, xv.z * dv.z, xv.w * dv.w };

#pragma unroll
    for (int c = 0; c < 4; ++c) {
        int h = h4 + c;
        int cnt = g_tap_cnt[h];
        if (cnt > 0) {                         // cold path (taps survive threshold)
            int l = m & (Lseq - 1);
            int b = m >> 13;
            const int* ti = g_tap_idx + (size_t)h * Lseq;
            const float* tv = g_tap_val + (size_t)h * Lseq;
            float acc = 0.0f;
            for (int t = 0; t < cnt; ++t) {
                int j = ti[t];
                if (j <= l)
                    acc += tv[t] * x[((size_t)b * Lseq + (l - j)) * Hd + h];
            }
            s[c] += acc;
        }
    }

    __half2 h01 = __floats2half2_rn(s[0] * sigmoidf_(s[0]), s[1] * sigmoidf_(s[1]));
    __half2 h23 = __floats2half2_rn(s[2] * sigmoidf_(s[2]), s[3] * sigmoidf_(s[3]));
    uint2 pk;
    pk.x = *reinterpret_cast<uint32_t*>(&h01);
    pk.y = *reinterpret_cast<uint32_t*>(&h23);
    *reinterpret_cast<uint2*>(g_vh + (size_t)m * Hd + h4) = pk;
}

// ---------------- kernel 3: fp16 mma GEMM (f16 acc) + bias + GLU + residual --
// CTA: 128 M-rows x (64 a-cols + matching 64 g-cols). B smem rows 0..63 = W row
// n0+r, rows 64..127 = W row 768+n0+r. GLU fused in epilogue.
__global__ void __launch_bounds__(256, 2)
gemm_fp16_kernel(const float* __restrict__ bias, const float* __restrict__ x,
                 float* __restrict__ out) {
    extern __shared__ char dsm[];
    uint32_t sb = s2u(dsm);
    const int tid  = threadIdx.x;
    const int lane = tid & 31;
    const int warp = tid >> 5;
    const int wm = warp >> 2;            // 0..1 -> 64 M-rows each
    const int wn = warp & 3;             // 0..3 -> 16 a-cols (+16 g-cols) each
    const int m0 = blockIdx.y * 128;
    const int n0 = blockIdx.x * 64;

    // global->smem loader mapping: each thread owns 2 A units + 2 B units/stage
    const int i0 = tid, i1 = tid + 256;
    const int ar0 = i0 >> 2, au0 = i0 & 3;
    const int ar1 = i1 >> 2, au1 = i1 & 3;
    const __half* asrc0 = g_vh + (size_t)(m0 + ar0) * Hd + au0 * 8;
    const __half* asrc1 = g_vh + (size_t)(m0 + ar1) * Hd + au1 * 8;
    const int wr0 = (ar0 < 64) ? (n0 + ar0) : (704 + n0 + ar0);
    const int wr1 = (ar1 < 64) ? (n0 + ar1) : (704 + n0 + ar1);
    const __half* bsrc0 = g_wh + (size_t)wr0 * Hd + au0 * 8;
    const __half* bsrc1 = g_wh + (size_t)wr1 * Hd + au1 * 8;
    const uint32_t ad0 = (uint32_t)(ar0 * RSB + au0 * 16);
    const uint32_t ad1 = (uint32_t)(ar1 * RSB + au1 * 16);

    // prologue: stages 0..2
#pragma unroll
    for (int s = 0; s < 3; ++s) {
        uint32_t st = sb + s * STG;
        cp16(st + ad0, asrc0 + s * 32);
        cp16(st + ad1, asrc1 + s * 32);
        cp16(st + ATILE + ad0, bsrc0 + s * 32);
        cp16(st + ATILE + ad1, bsrc1 + s * 32);
        asm volatile("cp.async.commit_group;" ::: "memory");
    }

    // ldmatrix per-lane offsets
    const int lro = (lane & 7) + ((lane >> 3) & 1) * 8;
    const int lu  = lane >> 4;
    uint32_t aoff[4], boff[2];
#pragma unroll
    for (int mi = 0; mi < 4; ++mi)
        aoff[mi] = (uint32_t)((wm * 64 + mi * 16 + lro) * RSB + lu * 16);
    boff[0] = (uint32_t)((wn * 16 + lro) * RSB + lu * 16);
    boff[1] = (uint32_t)((64 + wn * 16 + lro) * RSB + lu * 16);

    uint32_t accA[4][2][2], accG[4][2][2];    // f16x2 accumulators
#pragma unroll
    for (int mi = 0; mi < 4; ++mi)
#pragma unroll
        for (int nj = 0; nj < 2; ++nj)
#pragma unroll
            for (int r = 0; r < 2; ++r) { accA[mi][nj][r] = 0u; accG[mi][nj][r] = 0u; }

    for (int t = 0; t < KT; ++t) {
        asm volatile("cp.async.wait_group 2;" ::: "memory");
        __syncthreads();

        if (t + 3 < KT) {
            uint32_t st = sb + ((t + 3) & 3) * STG;
            int kw = (t + 3) * 32;
            cp16(st + ad0, asrc0 + kw);
            cp16(st + ad1, asrc1 + kw);
            cp16(st + ATILE + ad0, bsrc0 + kw);
            cp16(st + ATILE + ad1, bsrc1 + kw);
        }
        asm volatile("cp.async.commit_group;" ::: "memory");

        uint32_t ab = sb + (t & 3) * STG;
        uint32_t bb = ab + ATILE;
#pragma unroll
        for (int ks = 0; ks < 2; ++ks) {
            uint32_t kadd = (uint32_t)(ks * 32);   // 16 halves = 32B
            uint32_t afr[4][4];
#pragma unroll
            for (int mi = 0; mi < 4; ++mi)
                ldsm4(afr[mi], ab + aoff[mi] + kadd);
            uint32_t ba[4], bg[4];
            ldsm4(ba, bb + boff[0] + kadd);
            ldsm4(bg, bb + boff[1] + kadd);
#pragma unroll
            for (int mi = 0; mi < 4; ++mi) {
                mma16816h(accA[mi][0], afr[mi], ba[0], ba[2]);
                mma16816h(accA[mi][1], afr[mi], ba[1], ba[3]);
                mma16816h(accG[mi][0], afr[mi], bg[0], bg[2]);
                mma16816h(accG[mi][1], afr[mi], bg[1], bg[3]);
            }
        }
    }

    // epilogue: unpack f16 accs, bias + GLU + residual
    const int r  = lane >> 2;
    const int c2 = (lane & 3) * 2;
#pragma unroll
    for (int nj = 0; nj < 2; ++nj) {
        int col = n0 + wn * 16 + nj * 8 + c2;
        float ba0 = __ldg(bias + col),      ba1 = __ldg(bias + col + 1);
        float bg0 = __ldg(bias + Hd + col), bg1 = __ldg(bias + Hd + col + 1);
#pragma unroll
        for (int mi = 0; mi < 4; ++mi) {
            int mrow = m0 + wm * 64 + mi * 16 + r;
            {
                __half2 ah = *reinterpret_cast<__half2*>(&accA[mi][nj][0]);
                __half2 gh = *reinterpret_cast<__half2*>(&accG[mi][nj][0]);
                float a0 = __low2float(ah) + ba0, a1 = __high2float(ah) + ba1;
                float g0 = __low2float(gh) + bg0, g1 = __high2float(gh) + bg1;
                float2 xv = __ldg(reinterpret_cast<const float2*>(x + (size_t)mrow * Hd + col));
                float2 o;
                o.x = a0 * sigmoidf_(g0) + xv.x;
                o.y = a1 * sigmoidf_(g1) + xv.y;
                *reinterpret_cast<float2*>(out + (size_t)mrow * Hd + col) = o;
            }
            {
                int mr2 = mrow + 8;
                __half2 ah = *reinterpret_cast<__half2*>(&accA[mi][nj][1]);
                __half2 gh = *reinterpret_cast<__half2*>(&accG[mi][nj][1]);
                float a0 = __low2float(ah) + ba0, a1 = __high2float(ah) + ba1;
                float g0 = __low2float(gh) + bg0, g1 = __high2float(gh) + bg1;
                float2 xv = __ldg(reinterpret_cast<const float2*>(x + (size_t)mr2 * Hd + col));
                float2 o;
                o.x = a0 * sigmoidf_(g0) + xv.x;
                o.y = a1 * sigmoidf_(g1) + xv.y;
                *reinterpret_cast<float2*>(out + (size_t)mr2 * Hd + col) = o;
            }
        }
    }
}

// ---------------- launch ------------------------------------------------------
extern "C" void kernel_launch(void* const* d_in, const int* in_sizes, int n_in,
                              void* d_out, int out_size) {
    const float* x    = (const float*)d_in[0];   // (8, 8192, 768)
    const float* kern = (const float*)d_in[1];   // (1, 768, 8192)
    const float* D    = (const float*)d_in[2];   // (1, 768)
    const float* W    = (const float*)d_in[3];   // (1536, 768)
    const float* bias = (const float*)d_in[4];   // (1536,)
    float* out = (float*)d_out;                  // (8, 8192, 768)

    cudaFuncSetAttribute(gemm_fp16_kernel,
                         cudaFuncAttributeMaxDynamicSharedMemorySize, GSM);

    wconv_kernel<<<(2 * Hd * Hd) / 256, 256>>>(W);
    build_taps_kernel<<<Hd / 8, 256>>>(kern);

    int tot4 = Mtot * (Hd / 4);
    prep_v_kernel<<<tot4 / 256, 256>>>(x, D);

    dim3 grid(Hd / 64, Mtot / 128);              // (12, 512)
    gemm_fp16_kernel<<<grid, 256, GSM>>>(bias, x, out);
}

// round 11
// speedup vs baseline: 1.3936x; 1.0379x over previous
#include <cuda_runtime.h>
#include <cuda_fp16.h>
#include <cstdint>

// Problem constants
#define Bb   8
#define Lseq 8192
#define Hd   768
#define Mtot (Bb * Lseq)        // 65536
#define LAMK 0.1f

// GEMM tiling (fp16 mma.sync path, fp16 accumulate)
#define KT    24                // K chunks of 32
#define RSB   80                // smem row stride bytes (40 halves) -> conflict-free ldmatrix
#define ATILE 10240             // 128 rows * 80B
#define STG   20480             // A tile + B tile per stage
#define NSTG  3
#define GSM   (NSTG * STG)      // 61440 bytes dynamic smem -> 3 CTAs/SM

// ---------------- scratch ----------------------------------------------------
__device__ __half g_vh[(size_t)Mtot * Hd];      // silu(x*D + conv) in fp16
__device__ __half g_wh[2 * Hd * Hd];            // W in fp16 (1536 x 768)
__device__ int    g_tap_idx[Hd * Lseq];
__device__ float  g_tap_val[Hd * Lseq];
__device__ int    g_tap_cnt[Hd];

// ---------------- helpers ----------------------------------------------------
__device__ __forceinline__ float sigmoidf_(float z) {
    return 1.0f / (1.0f + __expf(-z));
}

__device__ __forceinline__ uint32_t s2u(const void* p) {
    uint32_t a;
    asm("{ .reg .u64 t; cvta.to.shared.u64 t, %1; cvt.u32.u64 %0, t; }"
        : "=r"(a) : "l"(p));
    return a;
}

__device__ __forceinline__ void cp16(uint32_t dst, const void* src) {
    asm volatile("cp.async.cg.shared.global [%0], [%1], 16;\n"
                 :: "r"(dst), "l"(src));
}

__device__ __forceinline__ void ldsm4(uint32_t* r, uint32_t addr) {
    asm volatile("ldmatrix.sync.aligned.m8n8.x4.shared.b16 {%0,%1,%2,%3}, [%4];"
                 : "=r"(r[0]), "=r"(r[1]), "=r"(r[2]), "=r"(r[3]) : "r"(addr));
}

// fp16-accumulate mma: D,C are 2 regs of f16x2
__device__ __forceinline__ void mma16816h(uint32_t* d, const uint32_t* a,
                                          uint32_t b0, uint32_t b1) {
    asm volatile(
        "mma.sync.aligned.m16n8k16.row.col.f16.f16.f16.f16 "
        "{%0,%1}, {%2,%3,%4,%5}, {%6,%7}, {%0,%1};\n"
        : "+r"(d[0]), "+r"(d[1])
        : "r"(a[0]), "r"(a[1]), "r"(a[2]), "r"(a[3]), "r"(b0), "r"(b1));
}

// ---------------- kernel 0: W fp32 -> fp16 -----------------------------------
__global__ void wconv_kernel(const float* __restrict__ W) {
    int i = blockIdx.x * 256 + threadIdx.x;
    g_wh[i] = __float2half_rn(W[i]);
}

// ---------------- kernel 1: soft-threshold + ordered tap compaction ----------
__global__ void build_taps_kernel(const float* __restrict__ kern) {
    int h = blockIdx.x * 8 + (threadIdx.x >> 5);
    int lane = threadIdx.x & 31;
    const float* kr = kern + (size_t)h * Lseq;
    int* ti = g_tap_idx + (size_t)h * Lseq;
    float* tv = g_tap_val + (size_t)h * Lseq;
    int cnt = 0;
    for (int base = 0; base < Lseq; base += 32) {
        float kv = kr[base + lane];
        float mag = fabsf(kv) - LAMK;
        bool p = mag > 0.0f;
        unsigned msk = __ballot_sync(0xffffffffu, p);
        if (p) {
            int pos = cnt + __popc(msk & ((1u << lane) - 1u));
            ti[pos] = base + lane;
            tv[pos] = copysignf(mag, kv);
        }
        cnt += __popc(msk);
    }
    if (lane == 0) g_tap_cnt[h] = cnt;
}

// ---------------- kernel 2: v = silu(x*D + sparse_causal_conv) -> fp16 -------
__global__ void prep_v_kernel(const float* __restrict__ x, const float* __restrict__ D) {
    const int H4 = Hd / 4;
    int i = blockIdx.x * blockDim.x + threadIdx.x;
    int m = i / H4;
    int h4 = (i - m * H4) * 4;

    float4 xv = *reinterpret_cast<const float4*>(x + (size_t)m * Hd + h4);
    float4 dv = *reinterpret_cast<const float4*>(D + h4);
    float s[4] = { xv.x * dv.x, xv.y * dv.y, xv.z * dv.z, xv.w * dv.w };

#pragma unroll
    for (int c = 0; c < 4; ++c) {
        int h = h4 + c;
        int cnt = g_tap_cnt[h];
        if (cnt > 0) {                         // cold path (taps survive threshold)
            int l = m & (Lseq - 1);
            int b = m >> 13;
            const int* ti = g_tap_idx + (size_t)h * Lseq;
            const float* tv = g_tap_val + (size_t)h * Lseq;
            float acc = 0.0f;
            for (int t = 0; t < cnt; ++t) {
                int j = ti[t];
                if (j <= l)
                    acc += tv[t] * x[((size_t)b * Lseq + (l - j)) * Hd + h];
            }
            s[c] += acc;
        }
    }

    __half2 h01 = __floats2half2_rn(s[0] * sigmoidf_(s[0]), s[1] * sigmoidf_(s[1]));
    __half2 h23 = __floats2half2_rn(s[2] * sigmoidf_(s[2]), s[3] * sigmoidf_(s[3]));
    uint2 pk;
    pk.x = *reinterpret_cast<uint32_t*>(&h01);
    pk.y = *reinterpret_cast<uint32_t*>(&h23);
    *reinterpret_cast<uint2*>(g_vh + (size_t)m * Hd + h4) = pk;
}

// ---------------- kernel 3: fp16 mma GEMM (f16 acc) + bias + GLU + residual --
// CTA: 128 M-rows x (64 a-cols + matching 64 g-cols). B smem rows 0..63 = W row
// n0+r, rows 64..127 = W row 768+n0+r. GLU fused in epilogue. 3 CTAs/SM.
__global__ void __launch_bounds__(256, 3)
gemm_fp16_kernel(const float* __restrict__ bias, const float* __restrict__ x,
                 float* __restrict__ out) {
    extern __shared__ char dsm[];
    uint32_t sb = s2u(dsm);
    const int tid  = threadIdx.x;
    const int lane = tid & 31;
    const int warp = tid >> 5;
    const int wm = warp >> 2;            // 0..1 -> 64 M-rows each
    const int wn = warp & 3;             // 0..3 -> 16 a-cols (+16 g-cols) each
    const int m0 = blockIdx.y * 128;
    const int n0 = blockIdx.x * 64;

    // global->smem loader mapping: each thread owns 2 A units + 2 B units/stage
    const int i0 = tid, i1 = tid + 256;
    const int ar0 = i0 >> 2, au0 = i0 & 3;
    const int ar1 = i1 >> 2, au1 = i1 & 3;
    const __half* asrc0 = g_vh + (size_t)(m0 + ar0) * Hd + au0 * 8;
    const __half* asrc1 = g_vh + (size_t)(m0 + ar1) * Hd + au1 * 8;
    const int wr0 = (ar0 < 64) ? (n0 + ar0) : (704 + n0 + ar0);
    const int wr1 = (ar1 < 64) ? (n0 + ar1) : (704 + n0 + ar1);
    const __half* bsrc0 = g_wh + (size_t)wr0 * Hd + au0 * 8;
    const __half* bsrc1 = g_wh + (size_t)wr1 * Hd + au1 * 8;
    const uint32_t ad0 = (uint32_t)(ar0 * RSB + au0 * 16);
    const uint32_t ad1 = (uint32_t)(ar1 * RSB + au1 * 16);

    // prologue: stages 0..1
#pragma unroll
    for (int s = 0; s < 2; ++s) {
        uint32_t st = sb + s * STG;
        cp16(st + ad0, asrc0 + s * 32);
        cp16(st + ad1, asrc1 + s * 32);
        cp16(st + ATILE + ad0, bsrc0 + s * 32);
        cp16(st + ATILE + ad1, bsrc1 + s * 32);
        asm volatile("cp.async.commit_group;" ::: "memory");
    }

    // ldmatrix per-lane offsets
    const int lro = (lane & 7) + ((lane >> 3) & 1) * 8;
    const int lu  = lane >> 4;
    uint32_t aoff[4], boff[2];
#pragma unroll
    for (int mi = 0; mi < 4; ++mi)
        aoff[mi] = (uint32_t)((wm * 64 + mi * 16 + lro) * RSB + lu * 16);
    boff[0] = (uint32_t)((wn * 16 + lro) * RSB + lu * 16);
    boff[1] = (uint32_t)((64 + wn * 16 + lro) * RSB + lu * 16);

    uint32_t accA[4][2][2], accG[4][2][2];    // f16x2 accumulators
#pragma unroll
    for (int mi = 0; mi < 4; ++mi)
#pragma unroll
        for (int nj = 0; nj < 2; ++nj)
#pragma unroll
            for (int r = 0; r < 2; ++r) { accA[mi][nj][r] = 0u; accG[mi][nj][r] = 0u; }

    for (int t = 0; t < KT; ++t) {
        asm volatile("cp.async.wait_group 1;" ::: "memory");
        __syncthreads();

        if (t + 2 < KT) {
            uint32_t st = sb + ((t + 2) % NSTG) * STG;
            int kw = (t + 2) * 32;
            cp16(st + ad0, asrc0 + kw);
            cp16(st + ad1, asrc1 + kw);
            cp16(st + ATILE + ad0, bsrc0 + kw);
            cp16(st + ATILE + ad1, bsrc1 + kw);
        }
        asm volatile("cp.async.commit_group;" ::: "memory");

        uint32_t ab = sb + (t % NSTG) * STG;
        uint32_t bb = ab + ATILE;
#pragma unroll
        for (int ks = 0; ks < 2; ++ks) {
            uint32_t kadd = (uint32_t)(ks * 32);   // 16 halves = 32B
            uint32_t afr[4][4];
#pragma unroll
            for (int mi = 0; mi < 4; ++mi)
                ldsm4(afr[mi], ab + aoff[mi] + kadd);
            uint32_t ba[4], bg[4];
            ldsm4(ba, bb + boff[0] + kadd);
            ldsm4(bg, bb + boff[1] + kadd);
#pragma unroll
            for (int mi = 0; mi < 4; ++mi) {
                mma16816h(accA[mi][0], afr[mi], ba[0], ba[2]);
                mma16816h(accA[mi][1], afr[mi], ba[1], ba[3]);
                mma16816h(accG[mi][0], afr[mi], bg[0], bg[2]);
                mma16816h(accG[mi][1], afr[mi], bg[1], bg[3]);
            }
        }
    }

    // epilogue: unpack f16 accs, bias + GLU + residual
    const int r  = lane >> 2;
    const int c2 = (lane & 3) * 2;
#pragma unroll
    for (int nj = 0; nj < 2; ++nj) {
        int col = n0 + wn * 16 + nj * 8 + c2;
        float ba0 = __ldg(bias + col),      ba1 = __ldg(bias + col + 1);
        float bg0 = __ldg(bias + Hd + col), bg1 = __ldg(bias + Hd + col + 1);
#pragma unroll
        for (int mi = 0; mi < 4; ++mi) {
            int mrow = m0 + wm * 64 + mi * 16 + r;
            {
                __half2 ah = *reinterpret_cast<__half2*>(&accA[mi][nj][0]);
                __half2 gh = *reinterpret_cast<__half2*>(&accG[mi][nj][0]);
                float a0 = __low2float(ah) + ba0, a1 = __high2float(ah) + ba1;
                float g0 = __low2float(gh) + bg0, g1 = __high2float(gh) + bg1;
                float2 xv = __ldg(reinterpret_cast<const float2*>(x + (size_t)mrow * Hd + col));
                float2 o;
                o.x = a0 * sigmoidf_(g0) + xv.x;
                o.y = a1 * sigmoidf_(g1) + xv.y;
                *reinterpret_cast<float2*>(out + (size_t)mrow * Hd + col) = o;
            }
            {
                int mr2 = mrow + 8;
                __half2 ah = *reinterpret_cast<__half2*>(&accA[mi][nj][1]);
                __half2 gh = *reinterpret_cast<__half2*>(&accG[mi][nj][1]);
                float a0 = __low2float(ah) + ba0, a1 = __high2float(ah) + ba1;
                float g0 = __low2float(gh) + bg0, g1 = __high2float(gh) + bg1;
                float2 xv = __ldg(reinterpret_cast<const float2*>(x + (size_t)mr2 * Hd + col));
                float2 o;
                o.x = a0 * sigmoidf_(g0) + xv.x;
                o.y = a1 * sigmoidf_(g1) + xv.y;
                *reinterpret_cast<float2*>(out + (size_t)mr2 * Hd + col) = o;
            }
        }
    }
}

// ---------------- launch ------------------------------------------------------
extern "C" void kernel_launch(void* const* d_in, const int* in_sizes, int n_in,
                              void* d_out, int out_size) {
    const float* x    = (const float*)d_in[0];   // (8, 8192, 768)
    const float* kern = (const float*)d_in[1];   // (1, 768, 8192)
    const float* D    = (const float*)d_in[2];   // (1, 768)
    const float* W    = (const float*)d_in[3];   // (1536, 768)
    const float* bias = (const float*)d_in[4];   // (1536,)
    float* out = (float*)d_out;                  // (8, 8192, 768)

    cudaFuncSetAttribute(gemm_fp16_kernel,
                         cudaFuncAttributeMaxDynamicSharedMemorySize, GSM);

    wconv_kernel<<<(2 * Hd * Hd) / 256, 256>>>(W);
    build_taps_kernel<<<Hd / 8, 256>>>(kern);

    int tot4 = Mtot * (Hd / 4);
    prep_v_kernel<<<tot4 / 256, 256>>>(x, D);

    dim3 grid(Hd / 64, Mtot / 128);              // (12, 512)
    gemm_fp16_kernel<<<grid, 256, GSM>>>(bias, x, out);
}